// round 3
// baseline (speedup 1.0000x reference)
#include <cuda_runtime.h>
#include <cstdint>

// Problem constants
#define BATCH 8
#define SEQ   1025
#define EMB   768
#define NH    12
#define HD    64
#define MROWS (BATCH*SEQ)      // 8200
#define NQKV  (3*EMB)          // 2304

// ---------------------------------------------------------------------------
// Scratch (device globals; allocation-free per harness rules)
// ---------------------------------------------------------------------------
__device__ float g_q [BATCH*NH*SEQ*HD];     // 25.2 MB, q pre-scaled
__device__ float g_k [BATCH*NH*SEQ*HD];
__device__ float g_v [BATCH*NH*SEQ*HD];
__device__ float g_ao[MROWS*EMB];           // attention output [B,N,C]
__device__ float g_rpb[NH*SEQ*SEQ];         // 50.4 MB rel-pos bias [H][N][N]

// ---------------------------------------------------------------------------
// Kernel 1: gather relative-position bias table -> dense [H][N][N]
// ---------------------------------------------------------------------------
__global__ void rpb_gather_kernel(const float* __restrict__ table,
                                  const int* __restrict__ relidx)
{
    int t = blockIdx.x * blockDim.x + threadIdx.x;
    const int total = NH * SEQ * SEQ;
    if (t >= total) return;
    int h  = t / (SEQ * SEQ);
    int qk = t - h * (SEQ * SEQ);
    g_rpb[t] = table[relidx[qk] * NH + h];
}

// ---------------------------------------------------------------------------
// Kernel 2: QKV GEMM  C[M=8200, N=2304] = X[M,768] @ W[N,768]^T (+bias, scatter)
// 128x128 tile, BK=16, 256 threads, 8x8 per thread
// ---------------------------------------------------------------------------
__global__ __launch_bounds__(256)
void qkv_gemm_kernel(const float* __restrict__ X,
                     const float* __restrict__ W,
                     const float* __restrict__ q_bias,
                     const float* __restrict__ v_bias)
{
    __shared__ float As[16][128];
    __shared__ float Bs[16][128];

    const int m0 = blockIdx.x * 128;
    const int n0 = blockIdx.y * 128;
    const int tid = threadIdx.x;
    const int tx = tid & 15;
    const int ty = tid >> 4;

    float acc[8][8];
    #pragma unroll
    for (int i = 0; i < 8; i++)
        #pragma unroll
        for (int j = 0; j < 8; j++) acc[i][j] = 0.f;

    for (int k0 = 0; k0 < EMB; k0 += 16) {
        // each thread loads 2 float4 from A and 2 from B
        #pragma unroll
        for (int rep = 0; rep < 2; rep++) {
            int f   = tid + rep * 256;        // 0..511
            int row = f >> 2;                 // 0..127
            int kc  = (f & 3) << 2;           // 0,4,8,12
            // A (guard M tail)
            float4 av;
            int gr = m0 + row;
            if (gr < MROWS) av = *(const float4*)&X[(size_t)gr * EMB + k0 + kc];
            else            av = make_float4(0.f, 0.f, 0.f, 0.f);
            As[kc + 0][row] = av.x; As[kc + 1][row] = av.y;
            As[kc + 2][row] = av.z; As[kc + 3][row] = av.w;
            // B (N = 2304 divisible by 128, no guard)
            float4 bv = *(const float4*)&W[(size_t)(n0 + row) * EMB + k0 + kc];
            Bs[kc + 0][row] = bv.x; Bs[kc + 1][row] = bv.y;
            Bs[kc + 2][row] = bv.z; Bs[kc + 3][row] = bv.w;
        }
        __syncthreads();

        #pragma unroll
        for (int kk = 0; kk < 16; kk++) {
            float4 a0 = *(const float4*)&As[kk][8 * ty];
            float4 a1 = *(const float4*)&As[kk][8 * ty + 4];
            float4 b0 = *(const float4*)&Bs[kk][8 * tx];
            float4 b1 = *(const float4*)&Bs[kk][8 * tx + 4];
            float a[8] = {a0.x, a0.y, a0.z, a0.w, a1.x, a1.y, a1.z, a1.w};
            float b[8] = {b0.x, b0.y, b0.z, b0.w, b1.x, b1.y, b1.z, b1.w};
            #pragma unroll
            for (int i = 0; i < 8; i++)
                #pragma unroll
                for (int j = 0; j < 8; j++)
                    acc[i][j] += a[i] * b[j];
        }
        __syncthreads();
    }

    // epilogue: bias + scale + scatter into [B][H][N][64] q/k/v buffers
    const float scale = 0.125f;   // 64^-0.5
    #pragma unroll
    for (int i = 0; i < 8; i++) {
        int gr = m0 + 8 * ty + i;
        if (gr >= MROWS) continue;
        int b = gr / SEQ;
        int n = gr - b * SEQ;
        #pragma unroll
        for (int j = 0; j < 8; j++) {
            int gc    = n0 + 8 * tx + j;
            int which = gc / EMB;
            int rem   = gc - which * EMB;
            int h     = rem >> 6;
            int d     = rem & 63;
            float val = acc[i][j];
            size_t off = ((size_t)(b * NH + h) * SEQ + n) * HD + d;
            if (which == 0)      g_q[off] = (val + q_bias[rem]) * scale;
            else if (which == 1) g_k[off] = val;
            else                 g_v[off] = val + v_bias[rem];
        }
    }
}

// ---------------------------------------------------------------------------
// Kernel 3: flash attention per (b, h, 128-query tile), key tiles of 64
// 256 threads: thread (ty=tid/16, tx=tid%16) owns queries 8*ty..+7,
// key/dim slots tx+16*j (j<4). Online softmax; RPB added from g_rpb.
// ---------------------------------------------------------------------------
#define QTILE 128
#define KTILE 64
// smem floats: sq[128*65] + sk[64*65] + sv[64*65] + sp[128*65]
#define ATTN_SMEM_FLOATS (QTILE*65 + KTILE*65 + KTILE*65 + QTILE*65)
#define ATTN_SMEM_BYTES  (ATTN_SMEM_FLOATS * 4)

__global__ __launch_bounds__(256)
void attn_kernel()
{
    extern __shared__ float sm[];
    float* sq = sm;                       // [128][65]
    float* sk = sq + QTILE * 65;          // [64][65]
    float* sv = sk + KTILE * 65;          // [64][65]
    float* sp = sv + KTILE * 65;          // [128][65]

    const int qt = blockIdx.x;
    const int h  = blockIdx.y;
    const int b  = blockIdx.z;
    const int q0 = qt * QTILE;
    const int tid = threadIdx.x;
    const int tx = tid & 15;
    const int ty = tid >> 4;

    const size_t bh = (size_t)(b * NH + h) * SEQ * HD;
    const float* qbase = g_q + bh;
    const float* kbase = g_k + bh;
    const float* vbase = g_v + bh;
    const float* rpbh  = g_rpb + (size_t)h * SEQ * SEQ;

    // load q tile (pitch 65, scalar smem stores)
    for (int f = tid; f < QTILE * 16; f += 256) {
        int row = f >> 4;
        int c4  = (f & 15) << 2;
        int qr  = q0 + row;
        float4 v4;
        if (qr < SEQ) v4 = *(const float4*)&qbase[(size_t)qr * HD + c4];
        else          v4 = make_float4(0.f, 0.f, 0.f, 0.f);
        float* dst = &sq[row * 65 + c4];
        dst[0] = v4.x; dst[1] = v4.y; dst[2] = v4.z; dst[3] = v4.w;
    }

    float m[8], l[8], acc[8][4];
    #pragma unroll
    for (int i = 0; i < 8; i++) {
        m[i] = -3.0e38f; l[i] = 0.f;
        #pragma unroll
        for (int j = 0; j < 4; j++) acc[i][j] = 0.f;
    }

    for (int k0 = 0; k0 < SEQ; k0 += KTILE) {
        __syncthreads();   // protects sk/sv/sp from previous iteration's reads
        // load k and v tiles
        for (int f = tid; f < KTILE * 16; f += 256) {
            int row = f >> 4;
            int c4  = (f & 15) << 2;
            int kr  = k0 + row;
            float4 kv, vv;
            if (kr < SEQ) {
                kv = *(const float4*)&kbase[(size_t)kr * HD + c4];
                vv = *(const float4*)&vbase[(size_t)kr * HD + c4];
            } else {
                kv = make_float4(0.f, 0.f, 0.f, 0.f);
                vv = kv;
            }
            float* dk = &sk[row * 65 + c4];
            dk[0] = kv.x; dk[1] = kv.y; dk[2] = kv.z; dk[3] = kv.w;
            float* dv = &sv[row * 65 + c4];
            dv[0] = vv.x; dv[1] = vv.y; dv[2] = vv.z; dv[3] = vv.w;
        }
        __syncthreads();

        // S = q @ k^T  (8x4 per thread)
        float s[8][4];
        #pragma unroll
        for (int i = 0; i < 8; i++)
            #pragma unroll
            for (int j = 0; j < 4; j++) s[i][j] = 0.f;

        #pragma unroll 8
        for (int d = 0; d < HD; d++) {
            float kreg[4];
            #pragma unroll
            for (int j = 0; j < 4; j++)
                kreg[j] = sk[(tx + 16 * j) * 65 + d];
            #pragma unroll
            for (int i = 0; i < 8; i++) {
                float qv = sq[(8 * ty + i) * 65 + d];
                #pragma unroll
                for (int j = 0; j < 4; j++)
                    s[i][j] += qv * kreg[j];
            }
        }

        // + relative position bias, mask invalid keys
        #pragma unroll
        for (int i = 0; i < 8; i++) {
            int qi = q0 + 8 * ty + i;
            if (qi >= SEQ) qi = SEQ - 1;               // clamp (row discarded)
            const float* rp = rpbh + (size_t)qi * SEQ;
            #pragma unroll
            for (int j = 0; j < 4; j++) {
                int kj = k0 + tx + 16 * j;
                if (kj < SEQ) s[i][j] += rp[kj];
                else          s[i][j] = -3.0e38f;
            }
        }

        // online softmax update (reduce over the 16 lanes sharing a q-row)
        #pragma unroll
        for (int i = 0; i < 8; i++) {
            float tm = fmaxf(fmaxf(s[i][0], s[i][1]), fmaxf(s[i][2], s[i][3]));
            #pragma unroll
            for (int off = 8; off >= 1; off >>= 1)
                tm = fmaxf(tm, __shfl_xor_sync(0xffffffffu, tm, off));
            float mn   = fmaxf(m[i], tm);
            float corr = __expf(m[i] - mn);
            float rs = 0.f;
            #pragma unroll
            for (int j = 0; j < 4; j++) {
                s[i][j] = __expf(s[i][j] - mn);
                rs += s[i][j];
            }
            #pragma unroll
            for (int off = 8; off >= 1; off >>= 1)
                rs += __shfl_xor_sync(0xffffffffu, rs, off);
            l[i] = l[i] * corr + rs;
            m[i] = mn;
            #pragma unroll
            for (int j = 0; j < 4; j++) acc[i][j] *= corr;
        }

        // publish P, then O += P @ V
        #pragma unroll
        for (int i = 0; i < 8; i++)
            #pragma unroll
            for (int j = 0; j < 4; j++)
                sp[(8 * ty + i) * 65 + tx + 16 * j] = s[i][j];
        __syncthreads();

        #pragma unroll 8
        for (int k = 0; k < KTILE; k++) {
            float vreg[4];
            #pragma unroll
            for (int j = 0; j < 4; j++)
                vreg[j] = sv[k * 65 + tx + 16 * j];
            #pragma unroll
            for (int i = 0; i < 8; i++) {
                float p = sp[(8 * ty + i) * 65 + k];
                #pragma unroll
                for (int j = 0; j < 4; j++)
                    acc[i][j] += p * vreg[j];
            }
        }
    }

    // normalize + write out in [B, N, H*64] layout (coalesced over tx)
    #pragma unroll
    for (int i = 0; i < 8; i++) {
        int qi = q0 + 8 * ty + i;
        if (qi >= SEQ) continue;
        float inv = 1.0f / l[i];
        #pragma unroll
        for (int j = 0; j < 4; j++)
            g_ao[((size_t)(b * SEQ + qi)) * EMB + h * HD + tx + 16 * j]
                = acc[i][j] * inv;
    }
}

// ---------------------------------------------------------------------------
// Kernel 4: projection GEMM  out[M,768] = AO[M,768] @ P[768,768]^T + proj_b
// ---------------------------------------------------------------------------
__global__ __launch_bounds__(256)
void proj_gemm_kernel(const float* __restrict__ W,
                      const float* __restrict__ bias,
                      float* __restrict__ out)
{
    __shared__ float As[16][128];
    __shared__ float Bs[16][128];

    const int m0 = blockIdx.x * 128;
    const int n0 = blockIdx.y * 128;
    const int tid = threadIdx.x;
    const int tx = tid & 15;
    const int ty = tid >> 4;

    float acc[8][8];
    #pragma unroll
    for (int i = 0; i < 8; i++)
        #pragma unroll
        for (int j = 0; j < 8; j++) acc[i][j] = 0.f;

    for (int k0 = 0; k0 < EMB; k0 += 16) {
        #pragma unroll
        for (int rep = 0; rep < 2; rep++) {
            int f   = tid + rep * 256;
            int row = f >> 2;
            int kc  = (f & 3) << 2;
            float4 av;
            int gr = m0 + row;
            if (gr < MROWS) av = *(const float4*)&g_ao[(size_t)gr * EMB + k0 + kc];
            else            av = make_float4(0.f, 0.f, 0.f, 0.f);
            As[kc + 0][row] = av.x; As[kc + 1][row] = av.y;
            As[kc + 2][row] = av.z; As[kc + 3][row] = av.w;
            float4 bv = *(const float4*)&W[(size_t)(n0 + row) * EMB + k0 + kc];
            Bs[kc + 0][row] = bv.x; Bs[kc + 1][row] = bv.y;
            Bs[kc + 2][row] = bv.z; Bs[kc + 3][row] = bv.w;
        }
        __syncthreads();

        #pragma unroll
        for (int kk = 0; kk < 16; kk++) {
            float4 a0 = *(const float4*)&As[kk][8 * ty];
            float4 a1 = *(const float4*)&As[kk][8 * ty + 4];
            float4 b0 = *(const float4*)&Bs[kk][8 * tx];
            float4 b1 = *(const float4*)&Bs[kk][8 * tx + 4];
            float a[8] = {a0.x, a0.y, a0.z, a0.w, a1.x, a1.y, a1.z, a1.w};
            float b[8] = {b0.x, b0.y, b0.z, b0.w, b1.x, b1.y, b1.z, b1.w};
            #pragma unroll
            for (int i = 0; i < 8; i++)
                #pragma unroll
                for (int j = 0; j < 8; j++)
                    acc[i][j] += a[i] * b[j];
        }
        __syncthreads();
    }

    #pragma unroll
    for (int i = 0; i < 8; i++) {
        int gr = m0 + 8 * ty + i;
        if (gr >= MROWS) continue;
        #pragma unroll
        for (int j = 0; j < 8; j++) {
            int gc = n0 + 8 * tx + j;
            out[(size_t)gr * EMB + gc] = acc[i][j] + bias[gc];
        }
    }
}

// ---------------------------------------------------------------------------
// Launch
// ---------------------------------------------------------------------------
extern "C" void kernel_launch(void* const* d_in, const int* in_sizes, int n_in,
                              void* d_out, int out_size)
{
    const float* x         = (const float*)d_in[0];
    const float* qkv_w     = (const float*)d_in[1];
    const float* q_bias    = (const float*)d_in[2];
    const float* v_bias    = (const float*)d_in[3];
    const float* rpb_table = (const float*)d_in[4];
    const float* proj_w    = (const float*)d_in[5];
    const float* proj_b    = (const float*)d_in[6];
    const int*   rel_idx   = (const int*)d_in[7];
    float*       out       = (float*)d_out;

    cudaFuncSetAttribute(attn_kernel,
                         cudaFuncAttributeMaxDynamicSharedMemorySize,
                         ATTN_SMEM_BYTES);

    // 1) RPB gather
    {
        const int total = NH * SEQ * SEQ;
        rpb_gather_kernel<<<(total + 255) / 256, 256>>>(rpb_table, rel_idx);
    }
    // 2) QKV GEMM
    {
        dim3 grid((MROWS + 127) / 128, NQKV / 128);
        qkv_gemm_kernel<<<grid, 256>>>(x, qkv_w, q_bias, v_bias);
    }
    // 3) flash attention
    {
        dim3 grid((SEQ + QTILE - 1) / QTILE, NH, BATCH);
        attn_kernel<<<grid, 256, ATTN_SMEM_BYTES>>>();
    }
    // 4) projection
    {
        dim3 grid((MROWS + 127) / 128, EMB / 128);
        proj_gemm_kernel<<<grid, 256>>>(proj_w, proj_b, out);
    }
}

// round 4
// speedup vs baseline: 1.6440x; 1.6440x over previous
#include <cuda_runtime.h>
#include <cstdint>

// Problem constants
#define BATCH 8
#define SEQ   1025
#define EMB   768
#define NH    12
#define HD    64
#define MROWS (BATCH*SEQ)      // 8200
#define NQKV  (3*EMB)          // 2304

// ---------------------------------------------------------------------------
// Scratch (device globals; allocation-free per harness rules)
// ---------------------------------------------------------------------------
__device__ float g_q [BATCH*NH*SEQ*HD];     // q pre-scaled
__device__ float g_k [BATCH*NH*SEQ*HD];
__device__ float g_v [BATCH*NH*SEQ*HD];
__device__ float g_ao[MROWS*EMB];           // attention output [B,N,C]
__device__ float g_rpb[NH*SEQ*SEQ];         // rel-pos bias [H][N][N]

// ---------------------------------------------------------------------------
// tf32 helpers
// ---------------------------------------------------------------------------
__device__ __forceinline__ float cvt_tf32(float x) {
    uint32_t u;
    asm("cvt.rna.tf32.f32 %0, %1;" : "=r"(u) : "f"(x));
    return __uint_as_float(u);
}

__device__ __forceinline__ void mma_tf32(float* d,
                                         const uint32_t* a,
                                         const uint32_t* b)
{
    asm volatile(
        "mma.sync.aligned.m16n8k8.row.col.f32.tf32.tf32.f32 "
        "{%0,%1,%2,%3}, {%4,%5,%6,%7}, {%8,%9}, {%0,%1,%2,%3};\n"
        : "+f"(d[0]), "+f"(d[1]), "+f"(d[2]), "+f"(d[3])
        : "r"(a[0]), "r"(a[1]), "r"(a[2]), "r"(a[3]),
          "r"(b[0]), "r"(b[1]));
}

// ---------------------------------------------------------------------------
// Kernel 1: gather relative-position bias table -> dense [H][N][N]
// ---------------------------------------------------------------------------
__global__ void rpb_gather_kernel(const float* __restrict__ table,
                                  const int* __restrict__ relidx)
{
    int t = blockIdx.x * blockDim.x + threadIdx.x;
    const int total = NH * SEQ * SEQ;
    if (t >= total) return;
    int h  = t / (SEQ * SEQ);
    int qk = t - h * (SEQ * SEQ);
    g_rpb[t] = table[relidx[qk] * NH + h];
}

// ---------------------------------------------------------------------------
// tf32 tensor-core GEMM core: 128x128 tile, BK=32, 256 thr, 8 warps x (64x32)
// As/Bs layout: [row][k] with pitch 36 (conflict-free fragment loads)
// ---------------------------------------------------------------------------
#define GP 36   // smem pitch in floats

// Kernel 2: QKV  C[M,2304] = X[M,768] @ W[2304,768]^T  (+bias, scale, scatter)
__global__ __launch_bounds__(256)
void qkv_gemm_tc(const float* __restrict__ X,
                 const float* __restrict__ W,
                 const float* __restrict__ q_bias,
                 const float* __restrict__ v_bias)
{
    __shared__ float As[128 * GP];
    __shared__ float Bs[128 * GP];

    const int m0  = blockIdx.x * 128;
    const int n0  = blockIdx.y * 128;
    const int tid = threadIdx.x;
    const int wid  = tid >> 5;
    const int lane = tid & 31;
    const int g  = lane >> 2;          // group id 0..7
    const int tg = lane & 3;           // thread-in-group 0..3
    const int wm = (wid >> 2) * 64;    // warp m offset within tile
    const int wn = (wid & 3) * 32;     // warp n offset within tile

    float acc[4][4][4];
    #pragma unroll
    for (int mi = 0; mi < 4; mi++)
        #pragma unroll
        for (int ni = 0; ni < 4; ni++)
            #pragma unroll
            for (int r = 0; r < 4; r++) acc[mi][ni][r] = 0.f;

    for (int k0 = 0; k0 < EMB; k0 += 32) {
        #pragma unroll
        for (int r = 0; r < 4; r++) {
            int f   = tid + r * 256;          // 0..1023
            int row = f >> 3;                 // 0..127
            int c4  = (f & 7) << 2;           // 0..28
            float4 av;
            int gr = m0 + row;
            if (gr < MROWS) av = *(const float4*)&X[(size_t)gr * EMB + k0 + c4];
            else            av = make_float4(0.f, 0.f, 0.f, 0.f);
            float* da = &As[row * GP + c4];
            da[0] = cvt_tf32(av.x); da[1] = cvt_tf32(av.y);
            da[2] = cvt_tf32(av.z); da[3] = cvt_tf32(av.w);
            float4 bv = *(const float4*)&W[(size_t)(n0 + row) * EMB + k0 + c4];
            float* db = &Bs[row * GP + c4];
            db[0] = cvt_tf32(bv.x); db[1] = cvt_tf32(bv.y);
            db[2] = cvt_tf32(bv.z); db[3] = cvt_tf32(bv.w);
        }
        __syncthreads();

        #pragma unroll
        for (int ks = 0; ks < 4; ks++) {
            const int kb = ks * 8;
            uint32_t afr[4][4];
            #pragma unroll
            for (int mi = 0; mi < 4; mi++) {
                int base = (wm + mi * 16 + g) * GP + kb + tg;
                afr[mi][0] = __float_as_uint(As[base]);
                afr[mi][1] = __float_as_uint(As[base + 8 * GP]);
                afr[mi][2] = __float_as_uint(As[base + 4]);
                afr[mi][3] = __float_as_uint(As[base + 8 * GP + 4]);
            }
            uint32_t bfr[4][2];
            #pragma unroll
            for (int ni = 0; ni < 4; ni++) {
                int base = (wn + ni * 8 + g) * GP + kb + tg;
                bfr[ni][0] = __float_as_uint(Bs[base]);
                bfr[ni][1] = __float_as_uint(Bs[base + 4]);
            }
            #pragma unroll
            for (int mi = 0; mi < 4; mi++)
                #pragma unroll
                for (int ni = 0; ni < 4; ni++)
                    mma_tf32(acc[mi][ni], afr[mi], bfr[ni]);
        }
        __syncthreads();
    }

    // epilogue: bias + scale + scatter into [B][H][N][64] q/k/v
    const float scale = 0.125f;
    #pragma unroll
    for (int mi = 0; mi < 4; mi++) {
        #pragma unroll
        for (int h2 = 0; h2 < 2; h2++) {
            int gr = m0 + wm + mi * 16 + g + h2 * 8;
            if (gr >= MROWS) continue;
            int b = gr / SEQ;
            int n = gr - b * SEQ;
            #pragma unroll
            for (int ni = 0; ni < 4; ni++) {
                int gc    = n0 + wn + ni * 8 + 2 * tg;   // even; pair {gc, gc+1}
                int which = gc / EMB;
                int rem   = gc - which * EMB;
                int h     = rem >> 6;
                int d     = rem & 63;
                float v0 = acc[mi][ni][h2 * 2 + 0];
                float v1 = acc[mi][ni][h2 * 2 + 1];
                size_t off = ((size_t)(b * NH + h) * SEQ + n) * HD + d;
                if (which == 0) {
                    float2 o = make_float2((v0 + q_bias[rem]) * scale,
                                           (v1 + q_bias[rem + 1]) * scale);
                    *(float2*)&g_q[off] = o;
                } else if (which == 1) {
                    *(float2*)&g_k[off] = make_float2(v0, v1);
                } else {
                    *(float2*)&g_v[off] = make_float2(v0 + v_bias[rem],
                                                      v1 + v_bias[rem + 1]);
                }
            }
        }
    }
}

// Kernel 4: proj  out[M,768] = AO[M,768] @ P[768,768]^T + bias
__global__ __launch_bounds__(256)
void proj_gemm_tc(const float* __restrict__ W,
                  const float* __restrict__ bias,
                  float* __restrict__ out)
{
    __shared__ float As[128 * GP];
    __shared__ float Bs[128 * GP];

    const int m0  = blockIdx.x * 128;
    const int n0  = blockIdx.y * 128;
    const int tid = threadIdx.x;
    const int wid  = tid >> 5;
    const int lane = tid & 31;
    const int g  = lane >> 2;
    const int tg = lane & 3;
    const int wm = (wid >> 2) * 64;
    const int wn = (wid & 3) * 32;

    float acc[4][4][4];
    #pragma unroll
    for (int mi = 0; mi < 4; mi++)
        #pragma unroll
        for (int ni = 0; ni < 4; ni++)
            #pragma unroll
            for (int r = 0; r < 4; r++) acc[mi][ni][r] = 0.f;

    for (int k0 = 0; k0 < EMB; k0 += 32) {
        #pragma unroll
        for (int r = 0; r < 4; r++) {
            int f   = tid + r * 256;
            int row = f >> 3;
            int c4  = (f & 7) << 2;
            float4 av;
            int gr = m0 + row;
            if (gr < MROWS) av = *(const float4*)&g_ao[(size_t)gr * EMB + k0 + c4];
            else            av = make_float4(0.f, 0.f, 0.f, 0.f);
            float* da = &As[row * GP + c4];
            da[0] = cvt_tf32(av.x); da[1] = cvt_tf32(av.y);
            da[2] = cvt_tf32(av.z); da[3] = cvt_tf32(av.w);
            float4 bv = *(const float4*)&W[(size_t)(n0 + row) * EMB + k0 + c4];
            float* db = &Bs[row * GP + c4];
            db[0] = cvt_tf32(bv.x); db[1] = cvt_tf32(bv.y);
            db[2] = cvt_tf32(bv.z); db[3] = cvt_tf32(bv.w);
        }
        __syncthreads();

        #pragma unroll
        for (int ks = 0; ks < 4; ks++) {
            const int kb = ks * 8;
            uint32_t afr[4][4];
            #pragma unroll
            for (int mi = 0; mi < 4; mi++) {
                int base = (wm + mi * 16 + g) * GP + kb + tg;
                afr[mi][0] = __float_as_uint(As[base]);
                afr[mi][1] = __float_as_uint(As[base + 8 * GP]);
                afr[mi][2] = __float_as_uint(As[base + 4]);
                afr[mi][3] = __float_as_uint(As[base + 8 * GP + 4]);
            }
            uint32_t bfr[4][2];
            #pragma unroll
            for (int ni = 0; ni < 4; ni++) {
                int base = (wn + ni * 8 + g) * GP + kb + tg;
                bfr[ni][0] = __float_as_uint(Bs[base]);
                bfr[ni][1] = __float_as_uint(Bs[base + 4]);
            }
            #pragma unroll
            for (int mi = 0; mi < 4; mi++)
                #pragma unroll
                for (int ni = 0; ni < 4; ni++)
                    mma_tf32(acc[mi][ni], afr[mi], bfr[ni]);
        }
        __syncthreads();
    }

    #pragma unroll
    for (int mi = 0; mi < 4; mi++) {
        #pragma unroll
        for (int h2 = 0; h2 < 2; h2++) {
            int gr = m0 + wm + mi * 16 + g + h2 * 8;
            if (gr >= MROWS) continue;
            #pragma unroll
            for (int ni = 0; ni < 4; ni++) {
                int gc = n0 + wn + ni * 8 + 2 * tg;
                float2 o = make_float2(acc[mi][ni][h2 * 2 + 0] + bias[gc],
                                       acc[mi][ni][h2 * 2 + 1] + bias[gc + 1]);
                *(float2*)&out[(size_t)gr * EMB + gc] = o;
            }
        }
    }
}

// ---------------------------------------------------------------------------
// Kernel 3: flash attention per (b, h, 128-query tile), key tiles of 64 (fp32)
// ---------------------------------------------------------------------------
#define QTILE 128
#define KTILE 64
#define ATTN_SMEM_FLOATS (QTILE*65 + KTILE*65 + KTILE*65 + QTILE*65)
#define ATTN_SMEM_BYTES  (ATTN_SMEM_FLOATS * 4)

__global__ __launch_bounds__(256)
void attn_kernel()
{
    extern __shared__ float sm[];
    float* sq = sm;                       // [128][65]
    float* sk = sq + QTILE * 65;          // [64][65]
    float* sv = sk + KTILE * 65;          // [64][65]
    float* sp = sv + KTILE * 65;          // [128][65]

    const int qt = blockIdx.x;
    const int h  = blockIdx.y;
    const int b  = blockIdx.z;
    const int q0 = qt * QTILE;
    const int tid = threadIdx.x;
    const int tx = tid & 15;
    const int ty = tid >> 4;

    const size_t bh = (size_t)(b * NH + h) * SEQ * HD;
    const float* qbase = g_q + bh;
    const float* kbase = g_k + bh;
    const float* vbase = g_v + bh;
    const float* rpbh  = g_rpb + (size_t)h * SEQ * SEQ;

    for (int f = tid; f < QTILE * 16; f += 256) {
        int row = f >> 4;
        int c4  = (f & 15) << 2;
        int qr  = q0 + row;
        float4 v4;
        if (qr < SEQ) v4 = *(const float4*)&qbase[(size_t)qr * HD + c4];
        else          v4 = make_float4(0.f, 0.f, 0.f, 0.f);
        float* dst = &sq[row * 65 + c4];
        dst[0] = v4.x; dst[1] = v4.y; dst[2] = v4.z; dst[3] = v4.w;
    }

    float m[8], l[8], acc[8][4];
    #pragma unroll
    for (int i = 0; i < 8; i++) {
        m[i] = -3.0e38f; l[i] = 0.f;
        #pragma unroll
        for (int j = 0; j < 4; j++) acc[i][j] = 0.f;
    }

    for (int k0 = 0; k0 < SEQ; k0 += KTILE) {
        __syncthreads();
        for (int f = tid; f < KTILE * 16; f += 256) {
            int row = f >> 4;
            int c4  = (f & 15) << 2;
            int kr  = k0 + row;
            float4 kv, vv;
            if (kr < SEQ) {
                kv = *(const float4*)&kbase[(size_t)kr * HD + c4];
                vv = *(const float4*)&vbase[(size_t)kr * HD + c4];
            } else {
                kv = make_float4(0.f, 0.f, 0.f, 0.f);
                vv = kv;
            }
            float* dk = &sk[row * 65 + c4];
            dk[0] = kv.x; dk[1] = kv.y; dk[2] = kv.z; dk[3] = kv.w;
            float* dv = &sv[row * 65 + c4];
            dv[0] = vv.x; dv[1] = vv.y; dv[2] = vv.z; dv[3] = vv.w;
        }
        __syncthreads();

        float s[8][4];
        #pragma unroll
        for (int i = 0; i < 8; i++)
            #pragma unroll
            for (int j = 0; j < 4; j++) s[i][j] = 0.f;

        #pragma unroll 8
        for (int d = 0; d < HD; d++) {
            float kreg[4];
            #pragma unroll
            for (int j = 0; j < 4; j++)
                kreg[j] = sk[(tx + 16 * j) * 65 + d];
            #pragma unroll
            for (int i = 0; i < 8; i++) {
                float qv = sq[(8 * ty + i) * 65 + d];
                #pragma unroll
                for (int j = 0; j < 4; j++)
                    s[i][j] += qv * kreg[j];
            }
        }

        #pragma unroll
        for (int i = 0; i < 8; i++) {
            int qi = q0 + 8 * ty + i;
            if (qi >= SEQ) qi = SEQ - 1;
            const float* rp = rpbh + (size_t)qi * SEQ;
            #pragma unroll
            for (int j = 0; j < 4; j++) {
                int kj = k0 + tx + 16 * j;
                if (kj < SEQ) s[i][j] += rp[kj];
                else          s[i][j] = -3.0e38f;
            }
        }

        #pragma unroll
        for (int i = 0; i < 8; i++) {
            float tm = fmaxf(fmaxf(s[i][0], s[i][1]), fmaxf(s[i][2], s[i][3]));
            #pragma unroll
            for (int off = 8; off >= 1; off >>= 1)
                tm = fmaxf(tm, __shfl_xor_sync(0xffffffffu, tm, off));
            float mn   = fmaxf(m[i], tm);
            float corr = __expf(m[i] - mn);
            float rs = 0.f;
            #pragma unroll
            for (int j = 0; j < 4; j++) {
                s[i][j] = __expf(s[i][j] - mn);
                rs += s[i][j];
            }
            #pragma unroll
            for (int off = 8; off >= 1; off >>= 1)
                rs += __shfl_xor_sync(0xffffffffu, rs, off);
            l[i] = l[i] * corr + rs;
            m[i] = mn;
            #pragma unroll
            for (int j = 0; j < 4; j++) acc[i][j] *= corr;
        }

        #pragma unroll
        for (int i = 0; i < 8; i++)
            #pragma unroll
            for (int j = 0; j < 4; j++)
                sp[(8 * ty + i) * 65 + tx + 16 * j] = s[i][j];
        __syncthreads();

        #pragma unroll 8
        for (int k = 0; k < KTILE; k++) {
            float vreg[4];
            #pragma unroll
            for (int j = 0; j < 4; j++)
                vreg[j] = sv[k * 65 + tx + 16 * j];
            #pragma unroll
            for (int i = 0; i < 8; i++) {
                float p = sp[(8 * ty + i) * 65 + k];
                #pragma unroll
                for (int j = 0; j < 4; j++)
                    acc[i][j] += p * vreg[j];
            }
        }
    }

    #pragma unroll
    for (int i = 0; i < 8; i++) {
        int qi = q0 + 8 * ty + i;
        if (qi >= SEQ) continue;
        float inv = 1.0f / l[i];
        #pragma unroll
        for (int j = 0; j < 4; j++)
            g_ao[((size_t)(b * SEQ + qi)) * EMB + h * HD + tx + 16 * j]
                = acc[i][j] * inv;
    }
}

// ---------------------------------------------------------------------------
// Launch
// ---------------------------------------------------------------------------
extern "C" void kernel_launch(void* const* d_in, const int* in_sizes, int n_in,
                              void* d_out, int out_size)
{
    const float* x         = (const float*)d_in[0];
    const float* qkv_w     = (const float*)d_in[1];
    const float* q_bias    = (const float*)d_in[2];
    const float* v_bias    = (const float*)d_in[3];
    const float* rpb_table = (const float*)d_in[4];
    const float* proj_w    = (const float*)d_in[5];
    const float* proj_b    = (const float*)d_in[6];
    const int*   rel_idx   = (const int*)d_in[7];
    float*       out       = (float*)d_out;

    cudaFuncSetAttribute(attn_kernel,
                         cudaFuncAttributeMaxDynamicSharedMemorySize,
                         ATTN_SMEM_BYTES);

    // 1) RPB gather
    {
        const int total = NH * SEQ * SEQ;
        rpb_gather_kernel<<<(total + 255) / 256, 256>>>(rpb_table, rel_idx);
    }
    // 2) QKV GEMM (tf32 tensor cores)
    {
        dim3 grid((MROWS + 127) / 128, NQKV / 128);
        qkv_gemm_tc<<<grid, 256>>>(x, qkv_w, q_bias, v_bias);
    }
    // 3) flash attention (fp32)
    {
        dim3 grid((SEQ + QTILE - 1) / QTILE, NH, BATCH);
        attn_kernel<<<grid, 256, ATTN_SMEM_BYTES>>>();
    }
    // 4) projection (tf32 tensor cores)
    {
        dim3 grid((MROWS + 127) / 128, EMB / 128);
        proj_gemm_tc<<<grid, 256>>>(proj_w, proj_b, out);
    }
}

// round 11
// speedup vs baseline: 3.0488x; 1.8545x over previous
#include <cuda_runtime.h>
#include <cstdint>

// Problem constants
#define BATCH 8
#define SEQ   1025
#define EMB   768
#define NH    12
#define HD    64
#define MROWS (BATCH*SEQ)      // 8200
#define NQKV  (3*EMB)          // 2304
#define RPP   1026             // RPB row pitch (even -> float2-aligned rows)

// ---------------------------------------------------------------------------
// Scratch (device globals; allocation-free per harness rules)
// ---------------------------------------------------------------------------
__device__ __align__(16) float g_q [BATCH*NH*SEQ*HD];   // q pre-scaled
__device__ __align__(16) float g_k [BATCH*NH*SEQ*HD];
__device__ __align__(16) float g_v [BATCH*NH*SEQ*HD];
__device__ __align__(16) float g_ao[MROWS*EMB];         // attention out [B,N,C]
__device__ __align__(16) float g_rpb[NH*SEQ*RPP + 256]; // [H][N][RPP] (+pad)

// ---------------------------------------------------------------------------
// tf32 helpers
// ---------------------------------------------------------------------------
__device__ __forceinline__ float cvt_tf32(float x) {
    uint32_t u;
    asm("cvt.rna.tf32.f32 %0, %1;" : "=r"(u) : "f"(x));
    return __uint_as_float(u);
}
__device__ __forceinline__ uint32_t cvt_tf32_u(float x) {
    uint32_t u;
    asm("cvt.rna.tf32.f32 %0, %1;" : "=r"(u) : "f"(x));
    return u;
}

__device__ __forceinline__ void mma_tf32(float* d,
                                         const uint32_t* a,
                                         const uint32_t* b)
{
    asm volatile(
        "mma.sync.aligned.m16n8k8.row.col.f32.tf32.tf32.f32 "
        "{%0,%1,%2,%3}, {%4,%5,%6,%7}, {%8,%9}, {%0,%1,%2,%3};\n"
        : "+f"(d[0]), "+f"(d[1]), "+f"(d[2]), "+f"(d[3])
        : "r"(a[0]), "r"(a[1]), "r"(a[2]), "r"(a[3]),
          "r"(b[0]), "r"(b[1]));
}

// ---------------------------------------------------------------------------
// Kernel 1: gather relative-position bias table -> dense [H][N][RPP]
// ---------------------------------------------------------------------------
__global__ void rpb_gather_kernel(const float* __restrict__ table,
                                  const int* __restrict__ relidx)
{
    int t = blockIdx.x * blockDim.x + threadIdx.x;
    const int total = NH * SEQ * SEQ;
    if (t >= total) return;
    int h  = t / (SEQ * SEQ);
    int qk = t - h * (SEQ * SEQ);
    int q  = qk / SEQ;
    int k  = qk - q * SEQ;
    g_rpb[((size_t)h * SEQ + q) * RPP + k] = table[relidx[qk] * NH + h];
}

// ---------------------------------------------------------------------------
// tf32 tensor-core GEMM core: 128x128 tile, BK=32, 256 thr, 8 warps x (64x32)
// ---------------------------------------------------------------------------
#define GP 36   // smem pitch in floats

// Kernel 2: QKV  C[M,2304] = X[M,768] @ W[2304,768]^T  (+bias, scale, scatter)
__global__ __launch_bounds__(256)
void qkv_gemm_tc(const float* __restrict__ X,
                 const float* __restrict__ W,
                 const float* __restrict__ q_bias,
                 const float* __restrict__ v_bias)
{
    __shared__ float As[128 * GP];
    __shared__ float Bs[128 * GP];

    const int m0  = blockIdx.x * 128;
    const int n0  = blockIdx.y * 128;
    const int tid = threadIdx.x;
    const int wid  = tid >> 5;
    const int lane = tid & 31;
    const int g  = lane >> 2;
    const int tg = lane & 3;
    const int wm = (wid >> 2) * 64;
    const int wn = (wid & 3) * 32;

    float acc[4][4][4];
    #pragma unroll
    for (int mi = 0; mi < 4; mi++)
        #pragma unroll
        for (int ni = 0; ni < 4; ni++)
            #pragma unroll
            for (int r = 0; r < 4; r++) acc[mi][ni][r] = 0.f;

    for (int k0 = 0; k0 < EMB; k0 += 32) {
        #pragma unroll
        for (int r = 0; r < 4; r++) {
            int f   = tid + r * 256;
            int row = f >> 3;
            int c4  = (f & 7) << 2;
            float4 av;
            int gr = m0 + row;
            if (gr < MROWS) av = *(const float4*)&X[(size_t)gr * EMB + k0 + c4];
            else            av = make_float4(0.f, 0.f, 0.f, 0.f);
            float* da = &As[row * GP + c4];
            da[0] = cvt_tf32(av.x); da[1] = cvt_tf32(av.y);
            da[2] = cvt_tf32(av.z); da[3] = cvt_tf32(av.w);
            float4 bv = *(const float4*)&W[(size_t)(n0 + row) * EMB + k0 + c4];
            float* db = &Bs[row * GP + c4];
            db[0] = cvt_tf32(bv.x); db[1] = cvt_tf32(bv.y);
            db[2] = cvt_tf32(bv.z); db[3] = cvt_tf32(bv.w);
        }
        __syncthreads();

        #pragma unroll
        for (int ks = 0; ks < 4; ks++) {
            const int kb = ks * 8;
            uint32_t afr[4][4];
            #pragma unroll
            for (int mi = 0; mi < 4; mi++) {
                int base = (wm + mi * 16 + g) * GP + kb + tg;
                afr[mi][0] = __float_as_uint(As[base]);
                afr[mi][1] = __float_as_uint(As[base + 8 * GP]);
                afr[mi][2] = __float_as_uint(As[base + 4]);
                afr[mi][3] = __float_as_uint(As[base + 8 * GP + 4]);
            }
            uint32_t bfr[4][2];
            #pragma unroll
            for (int ni = 0; ni < 4; ni++) {
                int base = (wn + ni * 8 + g) * GP + kb + tg;
                bfr[ni][0] = __float_as_uint(Bs[base]);
                bfr[ni][1] = __float_as_uint(Bs[base + 4]);
            }
            #pragma unroll
            for (int mi = 0; mi < 4; mi++)
                #pragma unroll
                for (int ni = 0; ni < 4; ni++)
                    mma_tf32(acc[mi][ni], afr[mi], bfr[ni]);
        }
        __syncthreads();
    }

    const float scale = 0.125f;
    #pragma unroll
    for (int mi = 0; mi < 4; mi++) {
        #pragma unroll
        for (int h2 = 0; h2 < 2; h2++) {
            int gr = m0 + wm + mi * 16 + g + h2 * 8;
            if (gr >= MROWS) continue;
            int b = gr / SEQ;
            int n = gr - b * SEQ;
            #pragma unroll
            for (int ni = 0; ni < 4; ni++) {
                int gc    = n0 + wn + ni * 8 + 2 * tg;
                int which = gc / EMB;
                int rem   = gc - which * EMB;
                int h     = rem >> 6;
                int d     = rem & 63;
                float v0 = acc[mi][ni][h2 * 2 + 0];
                float v1 = acc[mi][ni][h2 * 2 + 1];
                size_t off = ((size_t)(b * NH + h) * SEQ + n) * HD + d;
                if (which == 0) {
                    *(float2*)&g_q[off] = make_float2((v0 + q_bias[rem]) * scale,
                                                      (v1 + q_bias[rem + 1]) * scale);
                } else if (which == 1) {
                    *(float2*)&g_k[off] = make_float2(v0, v1);
                } else {
                    *(float2*)&g_v[off] = make_float2(v0 + v_bias[rem],
                                                      v1 + v_bias[rem + 1]);
                }
            }
        }
    }
}

// Kernel 4: proj  out[M,768] = AO[M,768] @ P[768,768]^T + bias
__global__ __launch_bounds__(256)
void proj_gemm_tc(const float* __restrict__ W,
                  const float* __restrict__ bias,
                  float* __restrict__ out)
{
    __shared__ float As[128 * GP];
    __shared__ float Bs[128 * GP];

    const int m0  = blockIdx.x * 128;
    const int n0  = blockIdx.y * 128;
    const int tid = threadIdx.x;
    const int wid  = tid >> 5;
    const int lane = tid & 31;
    const int g  = lane >> 2;
    const int tg = lane & 3;
    const int wm = (wid >> 2) * 64;
    const int wn = (wid & 3) * 32;

    float acc[4][4][4];
    #pragma unroll
    for (int mi = 0; mi < 4; mi++)
        #pragma unroll
        for (int ni = 0; ni < 4; ni++)
            #pragma unroll
            for (int r = 0; r < 4; r++) acc[mi][ni][r] = 0.f;

    for (int k0 = 0; k0 < EMB; k0 += 32) {
        #pragma unroll
        for (int r = 0; r < 4; r++) {
            int f   = tid + r * 256;
            int row = f >> 3;
            int c4  = (f & 7) << 2;
            float4 av;
            int gr = m0 + row;
            if (gr < MROWS) av = *(const float4*)&g_ao[(size_t)gr * EMB + k0 + c4];
            else            av = make_float4(0.f, 0.f, 0.f, 0.f);
            float* da = &As[row * GP + c4];
            da[0] = cvt_tf32(av.x); da[1] = cvt_tf32(av.y);
            da[2] = cvt_tf32(av.z); da[3] = cvt_tf32(av.w);
            float4 bv = *(const float4*)&W[(size_t)(n0 + row) * EMB + k0 + c4];
            float* db = &Bs[row * GP + c4];
            db[0] = cvt_tf32(bv.x); db[1] = cvt_tf32(bv.y);
            db[2] = cvt_tf32(bv.z); db[3] = cvt_tf32(bv.w);
        }
        __syncthreads();

        #pragma unroll
        for (int ks = 0; ks < 4; ks++) {
            const int kb = ks * 8;
            uint32_t afr[4][4];
            #pragma unroll
            for (int mi = 0; mi < 4; mi++) {
                int base = (wm + mi * 16 + g) * GP + kb + tg;
                afr[mi][0] = __float_as_uint(As[base]);
                afr[mi][1] = __float_as_uint(As[base + 8 * GP]);
                afr[mi][2] = __float_as_uint(As[base + 4]);
                afr[mi][3] = __float_as_uint(As[base + 8 * GP + 4]);
            }
            uint32_t bfr[4][2];
            #pragma unroll
            for (int ni = 0; ni < 4; ni++) {
                int base = (wn + ni * 8 + g) * GP + kb + tg;
                bfr[ni][0] = __float_as_uint(Bs[base]);
                bfr[ni][1] = __float_as_uint(Bs[base + 4]);
            }
            #pragma unroll
            for (int mi = 0; mi < 4; mi++)
                #pragma unroll
                for (int ni = 0; ni < 4; ni++)
                    mma_tf32(acc[mi][ni], afr[mi], bfr[ni]);
        }
        __syncthreads();
    }

    #pragma unroll
    for (int mi = 0; mi < 4; mi++) {
        #pragma unroll
        for (int h2 = 0; h2 < 2; h2++) {
            int gr = m0 + wm + mi * 16 + g + h2 * 8;
            if (gr >= MROWS) continue;
            #pragma unroll
            for (int ni = 0; ni < 4; ni++) {
                int gc = n0 + wn + ni * 8 + 2 * tg;
                *(float2*)&out[(size_t)gr * EMB + gc] =
                    make_float2(acc[mi][ni][h2 * 2 + 0] + bias[gc],
                                acc[mi][ni][h2 * 2 + 1] + bias[gc + 1]);
            }
        }
    }
}

// ---------------------------------------------------------------------------
// Kernel 3: tf32 tensor-core flash attention
// 8 warps; warp w owns query rows q0+16w..+15. S/P stay in registers; the
// P.V mma reuses the S accumulator (reg order c0,c2,c1,c3) against V rows
// 2tg/2tg+1 so both operand permutations cancel. smem pitch 68: sK fragment
// bank = 4g+tg, sV fragment bank = 8tg+g -> both conflict-free.
// ---------------------------------------------------------------------------
#define AQ 128
#define AK 64
#define AP 68
#define ATT_SMEM_BYTES ((AQ*AP + 2*AK*AP) * 4)   // 69632

__global__ __launch_bounds__(256, 2)
void attn_tc_kernel()
{
    extern __shared__ float sm[];
    float* sQ = sm;                 // [128][68] (tf32)
    float* sK = sQ + AQ * AP;       // [64][68]  (tf32)
    float* sV = sK + AK * AP;       // [64][68]  (tf32)

    const int qt = blockIdx.x;
    const int h  = blockIdx.y;
    const int b  = blockIdx.z;
    const int q0 = qt * AQ;
    const int tid  = threadIdx.x;
    const int w    = tid >> 5;
    const int lane = tid & 31;
    const int g  = lane >> 2;
    const int tg = lane & 3;

    const size_t bh = (size_t)(b * NH + h) * SEQ * HD;
    const float* qbase = g_q + bh;
    const float* kbase = g_k + bh;
    const float* vbase = g_v + bh;

    for (int f = tid; f < AQ * 16; f += 256) {
        int row = f >> 4;
        int c4  = (f & 15) << 2;
        int qr  = q0 + row;
        float4 v4;
        if (qr < SEQ) v4 = *(const float4*)&qbase[(size_t)qr * HD + c4];
        else          v4 = make_float4(0.f, 0.f, 0.f, 0.f);
        float* d = &sQ[row * AP + c4];
        d[0] = cvt_tf32(v4.x); d[1] = cvt_tf32(v4.y);
        d[2] = cvt_tf32(v4.z); d[3] = cvt_tf32(v4.w);
    }
    __syncthreads();

    uint32_t qf[8][4];
    #pragma unroll
    for (int c = 0; c < 8; c++) {
        int base = (16 * w + g) * AP + 8 * c + tg;
        qf[c][0] = __float_as_uint(sQ[base]);
        qf[c][1] = __float_as_uint(sQ[base + 8 * AP]);
        qf[c][2] = __float_as_uint(sQ[base + 4]);
        qf[c][3] = __float_as_uint(sQ[base + 8 * AP + 4]);
    }

    const int qi0 = q0 + 16 * w + g;
    const int qi1 = qi0 + 8;
    const int qc0 = (qi0 < SEQ) ? qi0 : (SEQ - 1);
    const int qc1 = (qi1 < SEQ) ? qi1 : (SEQ - 1);
    // RPB rows have even pitch RPP -> float2 reads at even kc are 8B-aligned
    const float* rp0 = g_rpb + ((size_t)h * SEQ + qc0) * RPP;
    const float* rp1 = g_rpb + ((size_t)h * SEQ + qc1) * RPP;

    float o[8][4];
    #pragma unroll
    for (int nj = 0; nj < 8; nj++)
        #pragma unroll
        for (int r = 0; r < 4; r++) o[nj][r] = 0.f;
    float m0r = -3.0e38f, m1r = -3.0e38f;
    float l0r = 0.f,      l1r = 0.f;

    for (int k0 = 0; k0 < SEQ; k0 += AK) {
        __syncthreads();
        for (int f = tid; f < AK * 16; f += 256) {
            int row = f >> 4;
            int c4  = (f & 15) << 2;
            int kr  = k0 + row;
            float4 kv, vv;
            if (kr < SEQ) {
                kv = *(const float4*)&kbase[(size_t)kr * HD + c4];
                vv = *(const float4*)&vbase[(size_t)kr * HD + c4];
            } else {
                kv = make_float4(0.f, 0.f, 0.f, 0.f);
                vv = kv;
            }
            float* dk = &sK[row * AP + c4];
            dk[0] = cvt_tf32(kv.x); dk[1] = cvt_tf32(kv.y);
            dk[2] = cvt_tf32(kv.z); dk[3] = cvt_tf32(kv.w);
            float* dv = &sV[row * AP + c4];
            dv[0] = cvt_tf32(vv.x); dv[1] = cvt_tf32(vv.y);
            dv[2] = cvt_tf32(vv.z); dv[3] = cvt_tf32(vv.w);
        }
        __syncthreads();

        // S = Q @ K^T (K natural [key][dim] layout is the col-major B operand)
        float s[8][4];
        #pragma unroll
        for (int nj = 0; nj < 8; nj++)
            #pragma unroll
            for (int r = 0; r < 4; r++) s[nj][r] = 0.f;

        #pragma unroll
        for (int c = 0; c < 8; c++) {
            #pragma unroll
            for (int nj = 0; nj < 8; nj++) {
                uint32_t bf[2];
                int ka = (8 * nj + g) * AP + 8 * c + tg;
                bf[0] = __float_as_uint(sK[ka]);
                bf[1] = __float_as_uint(sK[ka + 4]);
                mma_tf32(s[nj], qf[c], bf);
            }
        }

        // + relative position bias (accum cols are exactly 2tg, 2tg+1)
        #pragma unroll
        for (int nj = 0; nj < 8; nj++) {
            int kc = k0 + 8 * nj + 2 * tg;
            float2 r0v = *(const float2*)&rp0[kc];
            float2 r1v = *(const float2*)&rp1[kc];
            s[nj][0] += r0v.x; s[nj][1] += r0v.y;
            s[nj][2] += r1v.x; s[nj][3] += r1v.y;
        }
        // mask invalid keys (tail tile only); assignments overwrite any
        // garbage picked up from the padded RPB overread
        if (k0 + AK > SEQ) {
            #pragma unroll
            for (int nj = 0; nj < 8; nj++) {
                int kc = k0 + 8 * nj + 2 * tg;
                if (kc     >= SEQ) { s[nj][0] = -3.0e38f; s[nj][2] = -3.0e38f; }
                if (kc + 1 >= SEQ) { s[nj][1] = -3.0e38f; s[nj][3] = -3.0e38f; }
            }
        }

        // online softmax (row reductions across the 4 lanes of a quad)
        float tm0 = -3.0e38f, tm1 = -3.0e38f;
        #pragma unroll
        for (int nj = 0; nj < 8; nj++) {
            tm0 = fmaxf(tm0, fmaxf(s[nj][0], s[nj][1]));
            tm1 = fmaxf(tm1, fmaxf(s[nj][2], s[nj][3]));
        }
        #pragma unroll
        for (int off = 1; off <= 2; off <<= 1) {
            tm0 = fmaxf(tm0, __shfl_xor_sync(0xffffffffu, tm0, off));
            tm1 = fmaxf(tm1, __shfl_xor_sync(0xffffffffu, tm1, off));
        }
        float mn0 = fmaxf(m0r, tm0);
        float mn1 = fmaxf(m1r, tm1);
        float c0 = __expf(m0r - mn0);
        float c1 = __expf(m1r - mn1);
        m0r = mn0; m1r = mn1;

        float rs0 = 0.f, rs1 = 0.f;
        #pragma unroll
        for (int nj = 0; nj < 8; nj++) {
            s[nj][0] = __expf(s[nj][0] - mn0);
            s[nj][1] = __expf(s[nj][1] - mn0);
            s[nj][2] = __expf(s[nj][2] - mn1);
            s[nj][3] = __expf(s[nj][3] - mn1);
            rs0 += s[nj][0] + s[nj][1];
            rs1 += s[nj][2] + s[nj][3];
        }
        #pragma unroll
        for (int off = 1; off <= 2; off <<= 1) {
            rs0 += __shfl_xor_sync(0xffffffffu, rs0, off);
            rs1 += __shfl_xor_sync(0xffffffffu, rs1, off);
        }
        l0r = l0r * c0 + rs0;
        l1r = l1r * c1 + rs1;
        #pragma unroll
        for (int nj = 0; nj < 8; nj++) {
            o[nj][0] *= c0; o[nj][1] *= c0;
            o[nj][2] *= c1; o[nj][3] *= c1;
        }

        // O += P @ V : S accum feeds the A operand directly
        #pragma unroll
        for (int c = 0; c < 8; c++) {
            uint32_t pa[4];
            pa[0] = cvt_tf32_u(s[c][0]);
            pa[1] = cvt_tf32_u(s[c][2]);
            pa[2] = cvt_tf32_u(s[c][1]);
            pa[3] = cvt_tf32_u(s[c][3]);
            #pragma unroll
            for (int nj = 0; nj < 8; nj++) {
                uint32_t bf[2];
                int va = (8 * c + 2 * tg) * AP + 8 * nj + g;
                bf[0] = __float_as_uint(sV[va]);
                bf[1] = __float_as_uint(sV[va + AP]);
                mma_tf32(o[nj], pa, bf);
            }
        }
    }

    float inv0 = 1.0f / l0r;
    float inv1 = 1.0f / l1r;
    if (qi0 < SEQ) {
        float* dst = &g_ao[((size_t)(b * SEQ + qi0)) * EMB + h * HD];
        #pragma unroll
        for (int nj = 0; nj < 8; nj++)
            *(float2*)&dst[8 * nj + 2 * tg] =
                make_float2(o[nj][0] * inv0, o[nj][1] * inv0);
    }
    if (qi1 < SEQ) {
        float* dst = &g_ao[((size_t)(b * SEQ + qi1)) * EMB + h * HD];
        #pragma unroll
        for (int nj = 0; nj < 8; nj++)
            *(float2*)&dst[8 * nj + 2 * tg] =
                make_float2(o[nj][2] * inv1, o[nj][3] * inv1);
    }
}

// ---------------------------------------------------------------------------
// Launch
// ---------------------------------------------------------------------------
extern "C" void kernel_launch(void* const* d_in, const int* in_sizes, int n_in,
                              void* d_out, int out_size)
{
    const float* x         = (const float*)d_in[0];
    const float* qkv_w     = (const float*)d_in[1];
    const float* q_bias    = (const float*)d_in[2];
    const float* v_bias    = (const float*)d_in[3];
    const float* rpb_table = (const float*)d_in[4];
    const float* proj_w    = (const float*)d_in[5];
    const float* proj_b    = (const float*)d_in[6];
    const int*   rel_idx   = (const int*)d_in[7];
    float*       out       = (float*)d_out;

    cudaFuncSetAttribute(attn_tc_kernel,
                         cudaFuncAttributeMaxDynamicSharedMemorySize,
                         ATT_SMEM_BYTES);

    // 1) RPB gather
    {
        const int total = NH * SEQ * SEQ;
        rpb_gather_kernel<<<(total + 255) / 256, 256>>>(rpb_table, rel_idx);
    }
    // 2) QKV GEMM (tf32 tensor cores)
    {
        dim3 grid((MROWS + 127) / 128, NQKV / 128);
        qkv_gemm_tc<<<grid, 256>>>(x, qkv_w, q_bias, v_bias);
    }
    // 3) tf32 flash attention
    {
        dim3 grid((SEQ + AQ - 1) / AQ, NH, BATCH);
        attn_tc_kernel<<<grid, 256, ATT_SMEM_BYTES>>>();
    }
    // 4) projection (tf32 tensor cores)
    {
        dim3 grid((MROWS + 127) / 128, EMB / 128);
        proj_gemm_tc<<<grid, 256>>>(proj_w, proj_b, out);
    }
}

// round 12
// speedup vs baseline: 3.3161x; 1.0877x over previous
#include <cuda_runtime.h>
#include <cstdint>

// Problem constants
#define BATCH 8
#define SEQ   1025
#define EMB   768
#define NH    12
#define HD    64
#define MROWS (BATCH*SEQ)      // 8200
#define NQKV  (3*EMB)          // 2304
#define RPP   1026             // RPB row pitch (even -> float2-aligned rows)

// ---------------------------------------------------------------------------
// Scratch (device globals; allocation-free per harness rules)
// ---------------------------------------------------------------------------
__device__ __align__(16) float g_q  [BATCH*NH*SEQ*HD];   // q pre-scaled, tf32
__device__ __align__(16) float g_k  [BATCH*NH*SEQ*HD];   // tf32
__device__ __align__(16) float g_v  [BATCH*NH*SEQ*HD];   // tf32
__device__ __align__(16) float g_ao [MROWS*EMB];         // attn out, tf32
__device__ __align__(16) float g_rpb[NH*SEQ*RPP + 256];  // [H][N][RPP] (+pad)
__device__ __align__(16) float g_xt [MROWS*EMB];         // X  tf32-rounded
__device__ __align__(16) float g_wt [NQKV*EMB];          // qkv_w tf32-rounded
__device__ __align__(16) float g_pwt[EMB*EMB];           // proj_w tf32-rounded

// ---------------------------------------------------------------------------
// tf32 + cp.async helpers
// ---------------------------------------------------------------------------
__device__ __forceinline__ float cvt_tf32(float x) {
    uint32_t u;
    asm("cvt.rna.tf32.f32 %0, %1;" : "=r"(u) : "f"(x));
    return __uint_as_float(u);
}
__device__ __forceinline__ uint32_t cvt_tf32_u(float x) {
    uint32_t u;
    asm("cvt.rna.tf32.f32 %0, %1;" : "=r"(u) : "f"(x));
    return u;
}

__device__ __forceinline__ void mma_tf32(float* d,
                                         const uint32_t* a,
                                         const uint32_t* b)
{
    asm volatile(
        "mma.sync.aligned.m16n8k8.row.col.f32.tf32.tf32.f32 "
        "{%0,%1,%2,%3}, {%4,%5,%6,%7}, {%8,%9}, {%0,%1,%2,%3};\n"
        : "+f"(d[0]), "+f"(d[1]), "+f"(d[2]), "+f"(d[3])
        : "r"(a[0]), "r"(a[1]), "r"(a[2]), "r"(a[3]),
          "r"(b[0]), "r"(b[1]));
}

__device__ __forceinline__ void cp_async16(void* smem_dst, const void* gptr) {
    uint32_t sa = (uint32_t)__cvta_generic_to_shared(smem_dst);
    asm volatile("cp.async.cg.shared.global [%0], [%1], 16;\n"
                 :: "r"(sa), "l"(gptr));
}
#define CP_COMMIT()  asm volatile("cp.async.commit_group;\n")
#define CP_WAIT(N)   asm volatile("cp.async.wait_group %0;\n" :: "n"(N))

// ---------------------------------------------------------------------------
// Kernel 0: tf32 pre-round (vectorized, n % 4 == 0)
// ---------------------------------------------------------------------------
__global__ void tf32_round_kernel(const float* __restrict__ src,
                                  float* __restrict__ dst, int n4)
{
    int i = blockIdx.x * blockDim.x + threadIdx.x;
    if (i >= n4) return;
    float4 v = *(const float4*)&src[4 * i];
    v.x = cvt_tf32(v.x); v.y = cvt_tf32(v.y);
    v.z = cvt_tf32(v.z); v.w = cvt_tf32(v.w);
    *(float4*)&dst[4 * i] = v;
}

// ---------------------------------------------------------------------------
// Kernel 1: gather relative-position bias table -> dense [H][N][RPP]
// ---------------------------------------------------------------------------
__global__ void rpb_gather_kernel(const float* __restrict__ table,
                                  const int* __restrict__ relidx)
{
    int t = blockIdx.x * blockDim.x + threadIdx.x;
    const int total = NH * SEQ * SEQ;
    if (t >= total) return;
    int h  = t / (SEQ * SEQ);
    int qk = t - h * (SEQ * SEQ);
    int q  = qk / SEQ;
    int k  = qk - q * SEQ;
    g_rpb[((size_t)h * SEQ + q) * RPP + k] = table[relidx[qk] * NH + h];
}

// ---------------------------------------------------------------------------
// tf32 tensor-core GEMM: 128x128 tile, BK=32, 2-stage cp.async pipeline
// 256 thr, 8 warps x (64x32).  Inputs must be pre-rounded to tf32.
// ---------------------------------------------------------------------------
#define GP 36                       // smem pitch (floats); rows 16B-aligned
#define GSTG (128 * GP)             // floats per array per stage
#define GEMM_SMEM_BYTES (4 * GSTG * 4)   // As0,Bs0,As1,Bs1 = 73728 B
#define KBLK (EMB / 32)             // 24

// stage fill: A rows clamped to MROWS-1 (tail rows discarded in epilogue)
__device__ __forceinline__ void gemm_stage_load(
    float* As, float* Bs, const float* __restrict__ Agm,
    const float* __restrict__ Bgm, int m0, int n0, int k0, int tid)
{
    #pragma unroll
    for (int r = 0; r < 4; r++) {
        int f   = tid + r * 256;          // 0..1023
        int row = f >> 3;                 // 0..127
        int c4  = (f & 7) << 2;           // 0,4,..,28
        int gr  = m0 + row; if (gr > MROWS - 1) gr = MROWS - 1;
        cp_async16(&As[row * GP + c4], &Agm[(size_t)gr * EMB + k0 + c4]);
        cp_async16(&Bs[row * GP + c4], &Bgm[(size_t)(n0 + row) * EMB + k0 + c4]);
    }
}

__device__ __forceinline__ void gemm_stage_compute(
    const float* As, const float* Bs, float acc[4][4][4],
    int wm, int wn, int g, int tg)
{
    #pragma unroll
    for (int ks = 0; ks < 4; ks++) {
        const int kb = ks * 8;
        uint32_t afr[4][4];
        #pragma unroll
        for (int mi = 0; mi < 4; mi++) {
            int base = (wm + mi * 16 + g) * GP + kb + tg;
            afr[mi][0] = __float_as_uint(As[base]);
            afr[mi][1] = __float_as_uint(As[base + 8 * GP]);
            afr[mi][2] = __float_as_uint(As[base + 4]);
            afr[mi][3] = __float_as_uint(As[base + 8 * GP + 4]);
        }
        uint32_t bfr[4][2];
        #pragma unroll
        for (int ni = 0; ni < 4; ni++) {
            int base = (wn + ni * 8 + g) * GP + kb + tg;
            bfr[ni][0] = __float_as_uint(Bs[base]);
            bfr[ni][1] = __float_as_uint(Bs[base + 4]);
        }
        #pragma unroll
        for (int mi = 0; mi < 4; mi++)
            #pragma unroll
            for (int ni = 0; ni < 4; ni++)
                mma_tf32(acc[mi][ni], afr[mi], bfr[ni]);
    }
}

// Kernel 2: QKV  C[M,2304] = Xt[M,768] @ Wt[2304,768]^T (+bias/scale/scatter)
__global__ __launch_bounds__(256, 2)
void qkv_gemm_tc(const float* __restrict__ q_bias,
                 const float* __restrict__ v_bias)
{
    extern __shared__ float smp[];
    const int m0  = blockIdx.x * 128;
    const int n0  = blockIdx.y * 128;
    const int tid = threadIdx.x;
    const int wid  = tid >> 5;
    const int lane = tid & 31;
    const int g  = lane >> 2;
    const int tg = lane & 3;
    const int wm = (wid >> 2) * 64;
    const int wn = (wid & 3) * 32;

    float acc[4][4][4];
    #pragma unroll
    for (int mi = 0; mi < 4; mi++)
        #pragma unroll
        for (int ni = 0; ni < 4; ni++)
            #pragma unroll
            for (int r = 0; r < 4; r++) acc[mi][ni][r] = 0.f;

    gemm_stage_load(smp, smp + GSTG, g_xt, g_wt, m0, n0, 0, tid);
    CP_COMMIT();

    for (int it = 0; it < KBLK; it++) {
        float* As = smp + (it & 1) * 2 * GSTG;
        float* Bs = As + GSTG;
        if (it + 1 < KBLK) {
            float* An = smp + ((it + 1) & 1) * 2 * GSTG;
            gemm_stage_load(An, An + GSTG, g_xt, g_wt, m0, n0,
                            (it + 1) * 32, tid);
            CP_COMMIT();
            CP_WAIT(1);
        } else {
            CP_WAIT(0);
        }
        __syncthreads();
        gemm_stage_compute(As, Bs, acc, wm, wn, g, tg);
        __syncthreads();
    }

    const float scale = 0.125f;
    #pragma unroll
    for (int mi = 0; mi < 4; mi++) {
        #pragma unroll
        for (int h2 = 0; h2 < 2; h2++) {
            int gr = m0 + wm + mi * 16 + g + h2 * 8;
            if (gr >= MROWS) continue;
            int b = gr / SEQ;
            int n = gr - b * SEQ;
            #pragma unroll
            for (int ni = 0; ni < 4; ni++) {
                int gc    = n0 + wn + ni * 8 + 2 * tg;
                int which = gc / EMB;
                int rem   = gc - which * EMB;
                int h     = rem >> 6;
                int d     = rem & 63;
                float v0 = acc[mi][ni][h2 * 2 + 0];
                float v1 = acc[mi][ni][h2 * 2 + 1];
                size_t off = ((size_t)(b * NH + h) * SEQ + n) * HD + d;
                if (which == 0) {
                    *(float2*)&g_q[off] =
                        make_float2(cvt_tf32((v0 + q_bias[rem]) * scale),
                                    cvt_tf32((v1 + q_bias[rem + 1]) * scale));
                } else if (which == 1) {
                    *(float2*)&g_k[off] =
                        make_float2(cvt_tf32(v0), cvt_tf32(v1));
                } else {
                    *(float2*)&g_v[off] =
                        make_float2(cvt_tf32(v0 + v_bias[rem]),
                                    cvt_tf32(v1 + v_bias[rem + 1]));
                }
            }
        }
    }
}

// Kernel 4: proj  out[M,768] = AO[M,768] @ Pwt[768,768]^T + bias
__global__ __launch_bounds__(256, 2)
void proj_gemm_tc(const float* __restrict__ bias,
                  float* __restrict__ out)
{
    extern __shared__ float smp[];
    const int m0  = blockIdx.x * 128;
    const int n0  = blockIdx.y * 128;
    const int tid = threadIdx.x;
    const int wid  = tid >> 5;
    const int lane = tid & 31;
    const int g  = lane >> 2;
    const int tg = lane & 3;
    const int wm = (wid >> 2) * 64;
    const int wn = (wid & 3) * 32;

    float acc[4][4][4];
    #pragma unroll
    for (int mi = 0; mi < 4; mi++)
        #pragma unroll
        for (int ni = 0; ni < 4; ni++)
            #pragma unroll
            for (int r = 0; r < 4; r++) acc[mi][ni][r] = 0.f;

    gemm_stage_load(smp, smp + GSTG, g_ao, g_pwt, m0, n0, 0, tid);
    CP_COMMIT();

    for (int it = 0; it < KBLK; it++) {
        float* As = smp + (it & 1) * 2 * GSTG;
        float* Bs = As + GSTG;
        if (it + 1 < KBLK) {
            float* An = smp + ((it + 1) & 1) * 2 * GSTG;
            gemm_stage_load(An, An + GSTG, g_ao, g_pwt, m0, n0,
                            (it + 1) * 32, tid);
            CP_COMMIT();
            CP_WAIT(1);
        } else {
            CP_WAIT(0);
        }
        __syncthreads();
        gemm_stage_compute(As, Bs, acc, wm, wn, g, tg);
        __syncthreads();
    }

    #pragma unroll
    for (int mi = 0; mi < 4; mi++) {
        #pragma unroll
        for (int h2 = 0; h2 < 2; h2++) {
            int gr = m0 + wm + mi * 16 + g + h2 * 8;
            if (gr >= MROWS) continue;
            #pragma unroll
            for (int ni = 0; ni < 4; ni++) {
                int gc = n0 + wn + ni * 8 + 2 * tg;
                *(float2*)&out[(size_t)gr * EMB + gc] =
                    make_float2(acc[mi][ni][h2 * 2 + 0] + bias[gc],
                                acc[mi][ni][h2 * 2 + 1] + bias[gc + 1]);
            }
        }
    }
}

// ---------------------------------------------------------------------------
// Kernel 3: tf32 tensor-core flash attention (q/k/v arrive tf32-pre-rounded)
// ---------------------------------------------------------------------------
#define AQ 128
#define AK 64
#define AP 68
#define ATT_SMEM_BYTES ((AQ*AP + 2*AK*AP) * 4)   // 69632

__global__ __launch_bounds__(256, 2)
void attn_tc_kernel()
{
    extern __shared__ float sm[];
    float* sQ = sm;                 // [128][68]
    float* sK = sQ + AQ * AP;       // [64][68]
    float* sV = sK + AK * AP;       // [64][68]

    const int qt = blockIdx.x;
    const int h  = blockIdx.y;
    const int b  = blockIdx.z;
    const int q0 = qt * AQ;
    const int tid  = threadIdx.x;
    const int w    = tid >> 5;
    const int lane = tid & 31;
    const int g  = lane >> 2;
    const int tg = lane & 3;

    const size_t bh = (size_t)(b * NH + h) * SEQ * HD;
    const float* qbase = g_q + bh;
    const float* kbase = g_k + bh;
    const float* vbase = g_v + bh;

    for (int f = tid; f < AQ * 16; f += 256) {
        int row = f >> 4;
        int c4  = (f & 15) << 2;
        int qr  = q0 + row;
        float4 v4;
        if (qr < SEQ) v4 = *(const float4*)&qbase[(size_t)qr * HD + c4];
        else          v4 = make_float4(0.f, 0.f, 0.f, 0.f);
        *(float4*)&sQ[row * AP + c4] = v4;
    }
    __syncthreads();

    uint32_t qf[8][4];
    #pragma unroll
    for (int c = 0; c < 8; c++) {
        int base = (16 * w + g) * AP + 8 * c + tg;
        qf[c][0] = __float_as_uint(sQ[base]);
        qf[c][1] = __float_as_uint(sQ[base + 8 * AP]);
        qf[c][2] = __float_as_uint(sQ[base + 4]);
        qf[c][3] = __float_as_uint(sQ[base + 8 * AP + 4]);
    }

    const int qi0 = q0 + 16 * w + g;
    const int qi1 = qi0 + 8;
    const int qc0 = (qi0 < SEQ) ? qi0 : (SEQ - 1);
    const int qc1 = (qi1 < SEQ) ? qi1 : (SEQ - 1);
    const float* rp0 = g_rpb + ((size_t)h * SEQ + qc0) * RPP;
    const float* rp1 = g_rpb + ((size_t)h * SEQ + qc1) * RPP;

    float o[8][4];
    #pragma unroll
    for (int nj = 0; nj < 8; nj++)
        #pragma unroll
        for (int r = 0; r < 4; r++) o[nj][r] = 0.f;
    float m0r = -3.0e38f, m1r = -3.0e38f;
    float l0r = 0.f,      l1r = 0.f;

    for (int k0 = 0; k0 < SEQ; k0 += AK) {
        __syncthreads();
        for (int f = tid; f < AK * 16; f += 256) {
            int row = f >> 4;
            int c4  = (f & 15) << 2;
            int kr  = k0 + row;
            float4 kv, vv;
            if (kr < SEQ) {
                kv = *(const float4*)&kbase[(size_t)kr * HD + c4];
                vv = *(const float4*)&vbase[(size_t)kr * HD + c4];
            } else {
                kv = make_float4(0.f, 0.f, 0.f, 0.f);
                vv = kv;
            }
            *(float4*)&sK[row * AP + c4] = kv;
            *(float4*)&sV[row * AP + c4] = vv;
        }
        __syncthreads();

        float s[8][4];
        #pragma unroll
        for (int nj = 0; nj < 8; nj++)
            #pragma unroll
            for (int r = 0; r < 4; r++) s[nj][r] = 0.f;

        #pragma unroll
        for (int c = 0; c < 8; c++) {
            #pragma unroll
            for (int nj = 0; nj < 8; nj++) {
                uint32_t bf[2];
                int ka = (8 * nj + g) * AP + 8 * c + tg;
                bf[0] = __float_as_uint(sK[ka]);
                bf[1] = __float_as_uint(sK[ka + 4]);
                mma_tf32(s[nj], qf[c], bf);
            }
        }

        #pragma unroll
        for (int nj = 0; nj < 8; nj++) {
            int kc = k0 + 8 * nj + 2 * tg;
            float2 r0v = *(const float2*)&rp0[kc];
            float2 r1v = *(const float2*)&rp1[kc];
            s[nj][0] += r0v.x; s[nj][1] += r0v.y;
            s[nj][2] += r1v.x; s[nj][3] += r1v.y;
        }
        if (k0 + AK > SEQ) {
            #pragma unroll
            for (int nj = 0; nj < 8; nj++) {
                int kc = k0 + 8 * nj + 2 * tg;
                if (kc     >= SEQ) { s[nj][0] = -3.0e38f; s[nj][2] = -3.0e38f; }
                if (kc + 1 >= SEQ) { s[nj][1] = -3.0e38f; s[nj][3] = -3.0e38f; }
            }
        }

        float tm0 = -3.0e38f, tm1 = -3.0e38f;
        #pragma unroll
        for (int nj = 0; nj < 8; nj++) {
            tm0 = fmaxf(tm0, fmaxf(s[nj][0], s[nj][1]));
            tm1 = fmaxf(tm1, fmaxf(s[nj][2], s[nj][3]));
        }
        #pragma unroll
        for (int off = 1; off <= 2; off <<= 1) {
            tm0 = fmaxf(tm0, __shfl_xor_sync(0xffffffffu, tm0, off));
            tm1 = fmaxf(tm1, __shfl_xor_sync(0xffffffffu, tm1, off));
        }
        float mn0 = fmaxf(m0r, tm0);
        float mn1 = fmaxf(m1r, tm1);
        float c0 = __expf(m0r - mn0);
        float c1 = __expf(m1r - mn1);
        m0r = mn0; m1r = mn1;

        float rs0 = 0.f, rs1 = 0.f;
        #pragma unroll
        for (int nj = 0; nj < 8; nj++) {
            s[nj][0] = __expf(s[nj][0] - mn0);
            s[nj][1] = __expf(s[nj][1] - mn0);
            s[nj][2] = __expf(s[nj][2] - mn1);
            s[nj][3] = __expf(s[nj][3] - mn1);
            rs0 += s[nj][0] + s[nj][1];
            rs1 += s[nj][2] + s[nj][3];
        }
        #pragma unroll
        for (int off = 1; off <= 2; off <<= 1) {
            rs0 += __shfl_xor_sync(0xffffffffu, rs0, off);
            rs1 += __shfl_xor_sync(0xffffffffu, rs1, off);
        }
        l0r = l0r * c0 + rs0;
        l1r = l1r * c1 + rs1;
        #pragma unroll
        for (int nj = 0; nj < 8; nj++) {
            o[nj][0] *= c0; o[nj][1] *= c0;
            o[nj][2] *= c1; o[nj][3] *= c1;
        }

        #pragma unroll
        for (int c = 0; c < 8; c++) {
            uint32_t pa[4];
            pa[0] = cvt_tf32_u(s[c][0]);
            pa[1] = cvt_tf32_u(s[c][2]);
            pa[2] = cvt_tf32_u(s[c][1]);
            pa[3] = cvt_tf32_u(s[c][3]);
            #pragma unroll
            for (int nj = 0; nj < 8; nj++) {
                uint32_t bf[2];
                int va = (8 * c + 2 * tg) * AP + 8 * nj + g;
                bf[0] = __float_as_uint(sV[va]);
                bf[1] = __float_as_uint(sV[va + AP]);
                mma_tf32(o[nj], pa, bf);
            }
        }
    }

    // epilogue: normalize, tf32-round (for the proj GEMM), write [B,N,C]
    float inv0 = 1.0f / l0r;
    float inv1 = 1.0f / l1r;
    if (qi0 < SEQ) {
        float* dst = &g_ao[((size_t)(b * SEQ + qi0)) * EMB + h * HD];
        #pragma unroll
        for (int nj = 0; nj < 8; nj++)
            *(float2*)&dst[8 * nj + 2 * tg] =
                make_float2(cvt_tf32(o[nj][0] * inv0),
                            cvt_tf32(o[nj][1] * inv0));
    }
    if (qi1 < SEQ) {
        float* dst = &g_ao[((size_t)(b * SEQ + qi1)) * EMB + h * HD];
        #pragma unroll
        for (int nj = 0; nj < 8; nj++)
            *(float2*)&dst[8 * nj + 2 * tg] =
                make_float2(cvt_tf32(o[nj][2] * inv1),
                            cvt_tf32(o[nj][3] * inv1));
    }
}

// ---------------------------------------------------------------------------
// Launch
// ---------------------------------------------------------------------------
extern "C" void kernel_launch(void* const* d_in, const int* in_sizes, int n_in,
                              void* d_out, int out_size)
{
    const float* x         = (const float*)d_in[0];
    const float* qkv_w     = (const float*)d_in[1];
    const float* q_bias    = (const float*)d_in[2];
    const float* v_bias    = (const float*)d_in[3];
    const float* rpb_table = (const float*)d_in[4];
    const float* proj_w    = (const float*)d_in[5];
    const float* proj_b    = (const float*)d_in[6];
    const int*   rel_idx   = (const int*)d_in[7];
    float*       out       = (float*)d_out;

    cudaFuncSetAttribute(attn_tc_kernel,
                         cudaFuncAttributeMaxDynamicSharedMemorySize,
                         ATT_SMEM_BYTES);
    cudaFuncSetAttribute(qkv_gemm_tc,
                         cudaFuncAttributeMaxDynamicSharedMemorySize,
                         GEMM_SMEM_BYTES);
    cudaFuncSetAttribute(proj_gemm_tc,
                         cudaFuncAttributeMaxDynamicSharedMemorySize,
                         GEMM_SMEM_BYTES);

    // device-global targets for the prepass
    float *p_xt, *p_wt, *p_pwt;
    cudaGetSymbolAddress((void**)&p_xt,  g_xt);
    cudaGetSymbolAddress((void**)&p_wt,  g_wt);
    cudaGetSymbolAddress((void**)&p_pwt, g_pwt);

    // 0) tf32 pre-round of GEMM inputs
    {
        int n4 = MROWS * EMB / 4;
        tf32_round_kernel<<<(n4 + 255) / 256, 256>>>(x, p_xt, n4);
        n4 = NQKV * EMB / 4;
        tf32_round_kernel<<<(n4 + 255) / 256, 256>>>(qkv_w, p_wt, n4);
        n4 = EMB * EMB / 4;
        tf32_round_kernel<<<(n4 + 255) / 256, 256>>>(proj_w, p_pwt, n4);
    }
    // 1) RPB gather
    {
        const int total = NH * SEQ * SEQ;
        rpb_gather_kernel<<<(total + 255) / 256, 256>>>(rpb_table, rel_idx);
    }
    // 2) QKV GEMM (tf32 TC, cp.async double-buffered)
    {
        dim3 grid((MROWS + 127) / 128, NQKV / 128);
        qkv_gemm_tc<<<grid, 256, GEMM_SMEM_BYTES>>>(q_bias, v_bias);
    }
    // 3) tf32 flash attention
    {
        dim3 grid((SEQ + AQ - 1) / AQ, NH, BATCH);
        attn_tc_kernel<<<grid, 256, ATT_SMEM_BYTES>>>();
    }
    // 4) projection (tf32 TC, cp.async double-buffered)
    {
        dim3 grid((MROWS + 127) / 128, EMB / 128);
        proj_gemm_tc<<<grid, 256, GEMM_SMEM_BYTES>>>(proj_b, out);
    }
}